// round 1
// baseline (speedup 1.0000x reference)
#include <cuda_runtime.h>
#include <cstdint>

#define N_NODES_C 50000
#define N_EDGES_C 25000
#define MAX_ARITY 6
#define MAX_DEG 8
#define BATCH_C 4096

// ---------------- scratch (device globals; no allocations allowed) ----------------
__device__ __align__(256) float g_hn1[N_NODES_C * 256];   // layer1 node proj, [n][h*64+j]
__device__ __align__(256) float g_he1[N_EDGES_C * 256];   // layer1 edge proj
__device__ __align__(256) float g_eo1[N_EDGES_C * 256];   // layer1 edge_out (raw, pre-ELU)
__device__ __align__(256) float g_no1[N_NODES_C * 256];   // layer1 node_out (ELU applied)
__device__ __align__(256) float g_hn2[N_NODES_C * 128];
__device__ __align__(256) float g_he2[N_EDGES_C * 128];
__device__ __align__(256) float g_eo2[N_EDGES_C * 128];   // layer2 edge_out (raw)
__device__ __align__(256) float g_no2[N_NODES_C * 128];   // layer2 node_out (raw)
__device__ __align__(256) float g_WnCat[128 * 256];       // Wn repacked [k][h*64+j]
__device__ __align__(256) float g_WeCat[128 * 256];

// ---------------- helpers ----------------
__device__ __forceinline__ float warp_sum(float v) {
#pragma unroll
    for (int o = 16; o > 0; o >>= 1) v += __shfl_xor_sync(0xffffffffu, v, o);
    return v;
}
__device__ __forceinline__ float eluf(float x)  { return x > 0.f ? x : expm1f(x); }
__device__ __forceinline__ float lreluf(float x){ return x > 0.f ? x : 0.2f * x; }

// ---------------- weight repack: Wn/We [h][k][j] -> [k][h*64+j] ----------------
__global__ void repack_w(const float* __restrict__ Wn, const float* __restrict__ We) {
    int i = blockIdx.x * 256 + threadIdx.x;
    if (i >= 4 * 128 * 64) return;
    int h = i >> 13;          // / 8192
    int r = i & 8191;
    int k = r >> 6, j = r & 63;
    int o = k * 256 + h * 64 + j;
    g_WnCat[o] = Wn[i];
    g_WeCat[o] = We[i];
}

// ---------------- tiled fp32 GEMM: C[M,N] = act(A)[M,K] @ B[K,N] (row-major) -----
// BM=64, BN=64, BK=16, 256 threads, 4x4 micro-tile. K multiple of 16, N of 64.
template <bool ELU_A>
__global__ __launch_bounds__(256)
void gemm64(const float* __restrict__ A, const float* __restrict__ B,
            float* __restrict__ C, int M, int N, int K) {
    __shared__ float sA[16][64];   // [k][m]
    __shared__ float sB[16][64];   // [k][n]
    const int tid = threadIdx.x;
    const int bm = blockIdx.x * 64;
    const int bn = blockIdx.y * 64;
    const int tx = tid & 15, ty = tid >> 4;
    const int arow = tid >> 2, acol = (tid & 3) << 2;
    const int brow = tid >> 4, bcol = (tid & 15) << 2;
    const int grA = bm + arow;
    float acc[4][4] = {};
    for (int k0 = 0; k0 < K; k0 += 16) {
        float4 av = make_float4(0.f, 0.f, 0.f, 0.f);
        if (grA < M)
            av = *reinterpret_cast<const float4*>(A + (size_t)grA * K + (k0 + acol));
        if (ELU_A) { av.x = eluf(av.x); av.y = eluf(av.y); av.z = eluf(av.z); av.w = eluf(av.w); }
        sA[acol + 0][arow] = av.x; sA[acol + 1][arow] = av.y;
        sA[acol + 2][arow] = av.z; sA[acol + 3][arow] = av.w;
        float4 bv = *reinterpret_cast<const float4*>(B + (size_t)(k0 + brow) * N + (bn + bcol));
        *reinterpret_cast<float4*>(&sB[brow][bcol]) = bv;
        __syncthreads();
#pragma unroll
        for (int kk = 0; kk < 16; kk++) {
            float4 a4 = *reinterpret_cast<const float4*>(&sA[kk][ty << 2]);
            float4 b4 = *reinterpret_cast<const float4*>(&sB[kk][tx << 2]);
            acc[0][0] += a4.x * b4.x; acc[0][1] += a4.x * b4.y; acc[0][2] += a4.x * b4.z; acc[0][3] += a4.x * b4.w;
            acc[1][0] += a4.y * b4.x; acc[1][1] += a4.y * b4.y; acc[1][2] += a4.y * b4.z; acc[1][3] += a4.y * b4.w;
            acc[2][0] += a4.z * b4.x; acc[2][1] += a4.z * b4.y; acc[2][2] += a4.z * b4.z; acc[2][3] += a4.z * b4.w;
            acc[3][0] += a4.w * b4.x; acc[3][1] += a4.w * b4.y; acc[3][2] += a4.w * b4.z; acc[3][3] += a4.w * b4.w;
        }
        __syncthreads();
    }
#pragma unroll
    for (int i = 0; i < 4; i++) {
        int r = bm + (ty << 2) + i;
        if (r < M) {
            float4 o = make_float4(acc[i][0], acc[i][1], acc[i][2], acc[i][3]);
            *reinterpret_cast<float4*>(C + (size_t)r * N + bn + (tx << 2)) = o;
        }
    }
}

// ---------------- layer1 edge attention: warp per (edge, head), dim 64 ----------
__global__ __launch_bounds__(256)
void edge_attn_l1(const int* __restrict__ edge_list, const float* __restrict__ a1) {
    int w = blockIdx.x * 8 + (threadIdx.x >> 5);
    int lane = threadIdx.x & 31;
    int e = w >> 2, h = w & 3;
    if (e >= N_EDGES_C) return;
    const float* a = a1 + h * 128;
    float alo0 = a[lane], alo1 = a[lane + 32];
    float ahi0 = a[64 + lane], ahi1 = a[96 + lane];
    int base = e * 256 + h * 64;
    float se = warp_sum(g_he1[base + lane] * alo0 + g_he1[base + 32 + lane] * alo1);
    float nd0[MAX_ARITY], nd1[MAX_ARITY], s[MAX_ARITY];
#pragma unroll
    for (int ai = 0; ai < MAX_ARITY; ai++) {
        int id = edge_list[e * MAX_ARITY + ai];
        if (id > 0) {
            int nb = (id - 1) * 256 + h * 64;
            nd0[ai] = g_hn1[nb + lane];
            nd1[ai] = g_hn1[nb + 32 + lane];
            s[ai] = lreluf(se + warp_sum(nd0[ai] * ahi0 + nd1[ai] * ahi1));
        } else { nd0[ai] = 0.f; nd1[ai] = 0.f; s[ai] = -1e9f; }
    }
    float m = s[0];
#pragma unroll
    for (int ai = 1; ai < MAX_ARITY; ai++) m = fmaxf(m, s[ai]);
    float den = 0.f, o0 = 0.f, o1 = 0.f;
#pragma unroll
    for (int ai = 0; ai < MAX_ARITY; ai++) {
        float wg = expf(s[ai] - m);
        den += wg; o0 += wg * nd0[ai]; o1 += wg * nd1[ai];
    }
    float inv = 1.f / den;
    g_eo1[base + lane] = o0 * inv;
    g_eo1[base + 32 + lane] = o1 * inv;
}

// ---------------- layer1 node attention: warp per (node, head), dim 64, +ELU ----
__global__ __launch_bounds__(256)
void node_attn_l1(const int* __restrict__ node_list, const float* __restrict__ a2) {
    int w = blockIdx.x * 8 + (threadIdx.x >> 5);
    int lane = threadIdx.x & 31;
    int n = w >> 2, h = w & 3;
    if (n >= N_NODES_C) return;
    const float* a = a2 + h * 128;
    float alo0 = a[lane], alo1 = a[lane + 32];
    float ahi0 = a[64 + lane], ahi1 = a[96 + lane];
    int base = n * 256 + h * 64;
    float sn = warp_sum(g_hn1[base + lane] * alo0 + g_hn1[base + 32 + lane] * alo1);
    float ed0[MAX_DEG], ed1[MAX_DEG], s[MAX_DEG];
#pragma unroll
    for (int di = 0; di < MAX_DEG; di++) {
        int id = node_list[n * MAX_DEG + di];
        if (id > 0) {
            int eb = (id - 1) * 256 + h * 64;
            ed0[di] = g_eo1[eb + lane];
            ed1[di] = g_eo1[eb + 32 + lane];
            s[di] = lreluf(sn + warp_sum(ed0[di] * ahi0 + ed1[di] * ahi1));
        } else { ed0[di] = 0.f; ed1[di] = 0.f; s[di] = -1e9f; }
    }
    float m = s[0];
#pragma unroll
    for (int di = 1; di < MAX_DEG; di++) m = fmaxf(m, s[di]);
    float den = 0.f, o0 = 0.f, o1 = 0.f;
#pragma unroll
    for (int di = 0; di < MAX_DEG; di++) {
        float wg = expf(s[di] - m);
        den += wg; o0 += wg * ed0[di]; o1 += wg * ed1[di];
    }
    float inv = 1.f / den;
    g_no1[base + lane] = eluf(o0 * inv);
    g_no1[base + 32 + lane] = eluf(o1 * inv);
}

// ---------------- layer2 edge attention: warp per edge, dim 128 -----------------
__global__ __launch_bounds__(256)
void edge_attn_l2(const int* __restrict__ edge_list, const float* __restrict__ a1o) {
    int e = blockIdx.x * 8 + (threadIdx.x >> 5);
    int lane = threadIdx.x & 31;
    if (e >= N_EDGES_C) return;
    float alo[4], ahi[4], hev[4];
#pragma unroll
    for (int i = 0; i < 4; i++) {
        alo[i] = a1o[lane + 32 * i];
        ahi[i] = a1o[128 + lane + 32 * i];
        hev[i] = g_he2[e * 128 + lane + 32 * i];
    }
    float se = warp_sum(hev[0] * alo[0] + hev[1] * alo[1] + hev[2] * alo[2] + hev[3] * alo[3]);
    float nd[MAX_ARITY][4], s[MAX_ARITY];
#pragma unroll
    for (int ai = 0; ai < MAX_ARITY; ai++) {
        int id = edge_list[e * MAX_ARITY + ai];
        if (id > 0) {
            int nb = (id - 1) * 128;
            float p = 0.f;
#pragma unroll
            for (int i = 0; i < 4; i++) { nd[ai][i] = g_hn2[nb + lane + 32 * i]; p += nd[ai][i] * ahi[i]; }
            s[ai] = lreluf(se + warp_sum(p));
        } else {
#pragma unroll
            for (int i = 0; i < 4; i++) nd[ai][i] = 0.f;
            s[ai] = -1e9f;
        }
    }
    float m = s[0];
#pragma unroll
    for (int ai = 1; ai < MAX_ARITY; ai++) m = fmaxf(m, s[ai]);
    float den = 0.f, o[4] = {0.f, 0.f, 0.f, 0.f};
#pragma unroll
    for (int ai = 0; ai < MAX_ARITY; ai++) {
        float wg = expf(s[ai] - m);
        den += wg;
#pragma unroll
        for (int i = 0; i < 4; i++) o[i] += wg * nd[ai][i];
    }
    float inv = 1.f / den;
#pragma unroll
    for (int i = 0; i < 4; i++) g_eo2[e * 128 + lane + 32 * i] = o[i] * inv;
}

// ---------------- layer2 node attention: warp per node, dim 128 -----------------
__global__ __launch_bounds__(256)
void node_attn_l2(const int* __restrict__ node_list, const float* __restrict__ a2o) {
    int n = blockIdx.x * 8 + (threadIdx.x >> 5);
    int lane = threadIdx.x & 31;
    if (n >= N_NODES_C) return;
    float alo[4], ahi[4], hv[4];
#pragma unroll
    for (int i = 0; i < 4; i++) {
        alo[i] = a2o[lane + 32 * i];
        ahi[i] = a2o[128 + lane + 32 * i];
        hv[i] = g_hn2[n * 128 + lane + 32 * i];
    }
    float sn = warp_sum(hv[0] * alo[0] + hv[1] * alo[1] + hv[2] * alo[2] + hv[3] * alo[3]);
    float ed[MAX_DEG][4], s[MAX_DEG];
#pragma unroll
    for (int di = 0; di < MAX_DEG; di++) {
        int id = node_list[n * MAX_DEG + di];
        if (id > 0) {
            int eb = (id - 1) * 128;
            float p = 0.f;
#pragma unroll
            for (int i = 0; i < 4; i++) { ed[di][i] = g_eo2[eb + lane + 32 * i]; p += ed[di][i] * ahi[i]; }
            s[di] = lreluf(sn + warp_sum(p));
        } else {
#pragma unroll
            for (int i = 0; i < 4; i++) ed[di][i] = 0.f;
            s[di] = -1e9f;
        }
    }
    float m = s[0];
#pragma unroll
    for (int di = 1; di < MAX_DEG; di++) m = fmaxf(m, s[di]);
    float den = 0.f, o[4] = {0.f, 0.f, 0.f, 0.f};
#pragma unroll
    for (int di = 0; di < MAX_DEG; di++) {
        float wg = expf(s[di] - m);
        den += wg;
#pragma unroll
        for (int i = 0; i < 4; i++) o[i] += wg * ed[di][i];
    }
    float inv = 1.f / den;
#pragma unroll
    for (int i = 0; i < 4; i++) g_no2[n * 128 + lane + 32 * i] = o[i] * inv;
}

// ---------------- final batch gather (applies ELU to layer2 outputs) ------------
__global__ __launch_bounds__(128)
void gather_out(const int* __restrict__ bi, float* __restrict__ out) {
    int b = blockIdx.x;
    int t = threadIdx.x;   // 0..127
    __shared__ int ids[7];
    __shared__ int lastnz;
    if (t < 7) ids[t] = bi[b * 7 + t];
    __syncthreads();
    if (t == 0) {
        int ln = 0;
#pragma unroll
        for (int j = 1; j < 7; j++) if (ids[j] != 0) ln = j;
        lastnz = ln;
    }
    __syncthreads();
    int ln = lastnz;
    out[(size_t)b * 896 + t] = eluf(g_eo2[(size_t)(ids[0] - 1) * 128 + t]);
#pragma unroll
    for (int a = 1; a < 7; a++) {
        int nid = ids[a] - 1;
        if (nid < 0) nid += N_NODES_C;
        float g = eluf(g_no2[(size_t)nid * 128 + t]);
        out[(size_t)b * 896 + a * 128 + t] = (a <= ln) ? g : 1.0f;
    }
}

// ---------------- launch ----------------
extern "C" void kernel_launch(void* const* d_in, const int* in_sizes, int n_in,
                              void* d_out, int out_size) {
    (void)in_sizes; (void)n_in; (void)out_size;
    const int*   bi    = (const int*)d_in[0];
    const int*   el    = (const int*)d_in[1];
    const int*   nl    = (const int*)d_in[2];
    const float* nemb  = (const float*)d_in[3];
    const float* eemb  = (const float*)d_in[4];
    const float* Wn    = (const float*)d_in[5];
    const float* We    = (const float*)d_in[6];
    const float* a1    = (const float*)d_in[7];
    const float* a2    = (const float*)d_in[8];
    const float* Wn_o  = (const float*)d_in[9];
    const float* We_o  = (const float*)d_in[10];
    const float* a1_o  = (const float*)d_in[11];
    const float* a2_o  = (const float*)d_in[12];
    float* out = (float*)d_out;

    float *hn1, *he1, *eo1, *no1, *hn2, *he2, *wnc, *wec;
    cudaGetSymbolAddress((void**)&hn1, g_hn1);
    cudaGetSymbolAddress((void**)&he1, g_he1);
    cudaGetSymbolAddress((void**)&eo1, g_eo1);
    cudaGetSymbolAddress((void**)&no1, g_no1);
    cudaGetSymbolAddress((void**)&hn2, g_hn2);
    cudaGetSymbolAddress((void**)&he2, g_he2);
    cudaGetSymbolAddress((void**)&wnc, g_WnCat);
    cudaGetSymbolAddress((void**)&wec, g_WeCat);

    repack_w<<<128, 256>>>(Wn, We);

    // layer1 projections (heads packed into N=256)
    gemm64<false><<<dim3(782, 4), 256>>>(nemb, wnc, hn1, N_NODES_C, 256, 128);
    gemm64<false><<<dim3(391, 4), 256>>>(eemb, wec, he1, N_EDGES_C, 256, 128);

    edge_attn_l1<<<12500, 256>>>(el, a1);   // 25000 edges * 4 heads, warp each
    node_attn_l1<<<25000, 256>>>(nl, a2);   // 50000 nodes * 4 heads

    // layer2 projections (edge input gets ELU applied on the fly)
    gemm64<false><<<dim3(782, 2), 256>>>(no1, Wn_o, hn2, N_NODES_C, 128, 256);
    gemm64<true ><<<dim3(391, 2), 256>>>(eo1, We_o, he2, N_EDGES_C, 128, 256);

    edge_attn_l2<<<3125, 256>>>(el, a1_o);
    node_attn_l2<<<6250, 256>>>(nl, a2_o);

    gather_out<<<BATCH_C, 128>>>(bi, out);
}

// round 2
// speedup vs baseline: 1.6307x; 1.6307x over previous
#include <cuda_runtime.h>
#include <cstdint>

#define N_NODES_C 50000
#define N_EDGES_C 25000
#define MAX_ARITY 6
#define MAX_DEG 8
#define BATCH_C 4096

// ---------------- scratch (device globals; no allocations allowed) ----------------
__device__ __align__(256) float g_hn1[N_NODES_C * 256];   // layer1 node proj, [n][h*64+j]
__device__ __align__(256) float g_he1[N_EDGES_C * 256];   // layer1 edge proj
__device__ __align__(256) float g_eo1[N_EDGES_C * 256];   // layer1 edge_out (raw)
__device__ __align__(256) float g_no1[N_NODES_C * 256];   // layer1 node_out (ELU applied)
__device__ __align__(256) float g_hn2[N_NODES_C * 128];
__device__ __align__(256) float g_he2[N_EDGES_C * 128];
__device__ __align__(256) float g_eo2[N_EDGES_C * 128];   // layer2 edge_out (raw)
__device__ __align__(256) float g_no2[N_NODES_C * 128];   // layer2 node_out (raw)
__device__ __align__(256) float g_WnCat[128 * 256];       // Wn repacked [k][h*64+j]
__device__ __align__(256) float g_WeCat[128 * 256];
// scalar score caches
__device__ float g_pn1[N_NODES_C * 4];   // hn1 . a1[h, 64:128]
__device__ float g_sn1[N_NODES_C * 4];   // hn1 . a2[h, 0:64]
__device__ float g_se1[N_EDGES_C * 4];   // he1 . a1[h, 0:64]
__device__ float g_pe1[N_EDGES_C * 4];   // eo1 . a2[h, 64:128]
__device__ float g_pn2[N_NODES_C];       // hn2 . a1o[128:256]
__device__ float g_sn2[N_NODES_C];       // hn2 . a2o[0:128]
__device__ float g_se2[N_EDGES_C];       // he2 . a1o[0:128]
__device__ float g_pe2[N_EDGES_C];       // eo2 . a2o[128:256]

// ---------------- helpers ----------------
__device__ __forceinline__ float warp_sum(float v) {
#pragma unroll
    for (int o = 16; o > 0; o >>= 1) v += __shfl_xor_sync(0xffffffffu, v, o);
    return v;
}
__device__ __forceinline__ float seg8_sum(float v) {
#pragma unroll
    for (int o = 4; o > 0; o >>= 1) v += __shfl_xor_sync(0xffffffffu, v, o);
    return v;
}
__device__ __forceinline__ float eluf(float x)  { return x > 0.f ? x : expm1f(x); }
__device__ __forceinline__ float lreluf(float x){ return x > 0.f ? x : 0.2f * x; }
__device__ __forceinline__ unsigned f2tf(float x) {
    unsigned r; asm("cvt.rna.tf32.f32 %0, %1;" : "=r"(r) : "f"(x)); return r;
}
__device__ __forceinline__ void mma8(float c[4], unsigned a0, unsigned a1, unsigned a2,
                                     unsigned a3, unsigned b0, unsigned b1) {
    asm volatile(
        "mma.sync.aligned.m16n8k8.row.col.f32.tf32.tf32.f32 "
        "{%0,%1,%2,%3},{%4,%5,%6,%7},{%8,%9},{%0,%1,%2,%3};"
        : "+f"(c[0]), "+f"(c[1]), "+f"(c[2]), "+f"(c[3])
        : "r"(a0), "r"(a1), "r"(a2), "r"(a3), "r"(b0), "r"(b1));
}

// ---------------- weight repack: Wn/We [h][k][j] -> [k][h*64+j] ----------------
__global__ void repack_w(const float* __restrict__ Wn, const float* __restrict__ We) {
    int i = blockIdx.x * 256 + threadIdx.x;
    if (i >= 4 * 128 * 64) return;
    int h = i >> 13;
    int r = i & 8191;
    int k = r >> 6, j = r & 63;
    int o = k * 256 + h * 64 + j;
    g_WnCat[o] = Wn[i];
    g_WeCat[o] = We[i];
}

// ---------------- TF32 tensor-core GEMM: C[M,N] = act(A)[M,K] @ B[K,N] ----------
// BM=128, BN=64, BK=16, 256 threads = 8 warps (4m x 2n), warp tile 32x32.
template <bool ELU_A>
__global__ __launch_bounds__(256)
void gemm_tc(const float* __restrict__ A, const float* __restrict__ B,
             float* __restrict__ C, int M, int N, int K) {
    __shared__ unsigned As[128][20];   // [m][k], pad 20 -> conflict free frag loads
    __shared__ unsigned Bs[16][72];    // [k][n], pad 72
    const int tid = threadIdx.x;
    const int bm = blockIdx.x * 128, bn = blockIdx.y * 64;
    const int w = tid >> 5, lane = tid & 31;
    const int wm = (w >> 1) * 32, wn = (w & 1) * 32;
    const int gid = lane >> 2, tig = lane & 3;
    const int arow = tid >> 1, acg = (tid & 1) * 8;
    const int brow = tid >> 4, bcol = (tid & 15) * 4;
    const bool aval = (bm + arow) < M;
    const float* Ap = A + (size_t)(bm + arow) * K;
    float acc[2][4][4] = {};

    for (int k0 = 0; k0 < K; k0 += 16) {
        float4 v0 = make_float4(0.f, 0.f, 0.f, 0.f), v1 = v0;
        if (aval) {
            v0 = *reinterpret_cast<const float4*>(Ap + k0 + acg);
            v1 = *reinterpret_cast<const float4*>(Ap + k0 + acg + 4);
        }
        if (ELU_A) {
            v0.x = eluf(v0.x); v0.y = eluf(v0.y); v0.z = eluf(v0.z); v0.w = eluf(v0.w);
            v1.x = eluf(v1.x); v1.y = eluf(v1.y); v1.z = eluf(v1.z); v1.w = eluf(v1.w);
        }
        As[arow][acg + 0] = f2tf(v0.x); As[arow][acg + 1] = f2tf(v0.y);
        As[arow][acg + 2] = f2tf(v0.z); As[arow][acg + 3] = f2tf(v0.w);
        As[arow][acg + 4] = f2tf(v1.x); As[arow][acg + 5] = f2tf(v1.y);
        As[arow][acg + 6] = f2tf(v1.z); As[arow][acg + 7] = f2tf(v1.w);
        float4 bv = *reinterpret_cast<const float4*>(B + (size_t)(k0 + brow) * N + bn + bcol);
        Bs[brow][bcol + 0] = f2tf(bv.x); Bs[brow][bcol + 1] = f2tf(bv.y);
        Bs[brow][bcol + 2] = f2tf(bv.z); Bs[brow][bcol + 3] = f2tf(bv.w);
        __syncthreads();
#pragma unroll
        for (int kk = 0; kk < 16; kk += 8) {
            unsigned af[2][4], bf[4][2];
#pragma unroll
            for (int mt = 0; mt < 2; mt++) {
                int m0 = wm + mt * 16;
                af[mt][0] = As[m0 + gid][kk + tig];
                af[mt][1] = As[m0 + gid + 8][kk + tig];
                af[mt][2] = As[m0 + gid][kk + tig + 4];
                af[mt][3] = As[m0 + gid + 8][kk + tig + 4];
            }
#pragma unroll
            for (int nt = 0; nt < 4; nt++) {
                int n0 = wn + nt * 8;
                bf[nt][0] = Bs[kk + tig][n0 + gid];
                bf[nt][1] = Bs[kk + tig + 4][n0 + gid];
            }
#pragma unroll
            for (int mt = 0; mt < 2; mt++)
#pragma unroll
                for (int nt = 0; nt < 4; nt++)
                    mma8(acc[mt][nt], af[mt][0], af[mt][1], af[mt][2], af[mt][3],
                         bf[nt][0], bf[nt][1]);
        }
        __syncthreads();
    }
#pragma unroll
    for (int mt = 0; mt < 2; mt++) {
#pragma unroll
        for (int nt = 0; nt < 4; nt++) {
            int r0 = bm + wm + mt * 16 + gid;
            int c = bn + wn + nt * 8 + tig * 2;
            if (r0 < M)
                *reinterpret_cast<float2*>(C + (size_t)r0 * N + c) =
                    make_float2(acc[mt][nt][0], acc[mt][nt][1]);
            int r1 = r0 + 8;
            if (r1 < M)
                *reinterpret_cast<float2*>(C + (size_t)r1 * N + c) =
                    make_float2(acc[mt][nt][2], acc[mt][nt][3]);
        }
    }
}

// ------------- scalar score precompute, 256-wide rows (4 heads x 64) ------------
// P[r*4+h] = row . A[h*128 + aoff : +64];  optional Q with B/boff.
__global__ __launch_bounds__(256)
void scal64(const float* __restrict__ H, int M,
            const float* __restrict__ A, int aoff, float* __restrict__ P,
            const float* __restrict__ B, int boff, float* __restrict__ Q) {
    int r = blockIdx.x * 8 + (threadIdx.x >> 5);
    if (r >= M) return;
    int lane = threadIdx.x & 31;
    int h = lane >> 3, jl = lane & 7;
    const float* row = H + (size_t)r * 256 + lane * 8;
    float p = 0.f, q = 0.f;
#pragma unroll
    for (int i = 0; i < 8; i++) {
        float v = row[i];
        p += v * A[h * 128 + aoff + jl * 8 + i];
        if (B) q += v * B[h * 128 + boff + jl * 8 + i];
    }
    p = seg8_sum(p);
    if (B) q = seg8_sum(q);
    if (jl == 0) {
        P[r * 4 + h] = p;
        if (Q) Q[r * 4 + h] = q;
    }
}

// ------------- scalar score precompute, 128-wide rows ---------------------------
__global__ __launch_bounds__(256)
void scal128(const float* __restrict__ H, int M,
             const float* __restrict__ A, int aoff, float* __restrict__ P,
             const float* __restrict__ B, int boff, float* __restrict__ Q) {
    int r = blockIdx.x * 8 + (threadIdx.x >> 5);
    if (r >= M) return;
    int lane = threadIdx.x & 31;
    const float* row = H + (size_t)r * 128 + lane * 4;
    float p = 0.f, q = 0.f;
#pragma unroll
    for (int i = 0; i < 4; i++) {
        float v = row[i];
        p += v * A[aoff + lane * 4 + i];
        if (B) q += v * B[boff + lane * 4 + i];
    }
    p = warp_sum(p);
    if (B) q = warp_sum(q);
    if (lane == 0) {
        P[r] = p;
        if (Q) Q[r] = q;
    }
}

// ---------------- layer1 edge attention: warp per edge, all 4 heads -------------
__global__ __launch_bounds__(256)
void edge_attn1(const int* __restrict__ el, const float* __restrict__ a2) {
    int e = blockIdx.x * 8 + (threadIdx.x >> 5);
    if (e >= N_EDGES_C) return;
    int lane = threadIdx.x & 31;
    int h = lane >> 3, jl = lane & 7;
    float se = g_se1[e * 4 + h];
    int ids[MAX_ARITY];
    float s[MAX_ARITY];
#pragma unroll
    for (int ai = 0; ai < MAX_ARITY; ai++) ids[ai] = el[e * MAX_ARITY + ai];
#pragma unroll
    for (int ai = 0; ai < MAX_ARITY; ai++)
        s[ai] = (ids[ai] > 0) ? lreluf(se + g_pn1[(ids[ai] - 1) * 4 + h]) : -1e9f;
    float m = s[0];
#pragma unroll
    for (int ai = 1; ai < MAX_ARITY; ai++) m = fmaxf(m, s[ai]);
    float wv[MAX_ARITY], den = 0.f;
#pragma unroll
    for (int ai = 0; ai < MAX_ARITY; ai++) { wv[ai] = expf(s[ai] - m); den += wv[ai]; }
    float inv = 1.f / den;
    float o[8] = {};
#pragma unroll
    for (int ai = 0; ai < MAX_ARITY; ai++) {
        if (ids[ai] > 0) {
            const float4* p = reinterpret_cast<const float4*>(
                g_hn1 + (size_t)(ids[ai] - 1) * 256 + lane * 8);
            float4 x = p[0], y = p[1];
            float wg = wv[ai] * inv;
            o[0] += wg * x.x; o[1] += wg * x.y; o[2] += wg * x.z; o[3] += wg * x.w;
            o[4] += wg * y.x; o[5] += wg * y.y; o[6] += wg * y.z; o[7] += wg * y.w;
        }
    }
    float* dst = g_eo1 + (size_t)e * 256 + lane * 8;
    *reinterpret_cast<float4*>(dst)     = make_float4(o[0], o[1], o[2], o[3]);
    *reinterpret_cast<float4*>(dst + 4) = make_float4(o[4], o[5], o[6], o[7]);
    // epilogue: pe1[e,h] = edge_out . a2[h, 64:128]
    float pe = 0.f;
#pragma unroll
    for (int i = 0; i < 8; i++) pe += o[i] * a2[h * 128 + 64 + jl * 8 + i];
    pe = seg8_sum(pe);
    if (jl == 0) g_pe1[e * 4 + h] = pe;
}

// ---------------- layer1 node attention: warp per node, +ELU --------------------
__global__ __launch_bounds__(256)
void node_attn1(const int* __restrict__ nl) {
    int n = blockIdx.x * 8 + (threadIdx.x >> 5);
    if (n >= N_NODES_C) return;
    int lane = threadIdx.x & 31;
    int h = lane >> 3;
    float sn = g_sn1[n * 4 + h];
    int ids[MAX_DEG];
    float s[MAX_DEG];
#pragma unroll
    for (int di = 0; di < MAX_DEG; di++) ids[di] = nl[n * MAX_DEG + di];
#pragma unroll
    for (int di = 0; di < MAX_DEG; di++)
        s[di] = (ids[di] > 0) ? lreluf(sn + g_pe1[(ids[di] - 1) * 4 + h]) : -1e9f;
    float m = s[0];
#pragma unroll
    for (int di = 1; di < MAX_DEG; di++) m = fmaxf(m, s[di]);
    float wv[MAX_DEG], den = 0.f;
#pragma unroll
    for (int di = 0; di < MAX_DEG; di++) { wv[di] = expf(s[di] - m); den += wv[di]; }
    float inv = 1.f / den;
    float o[8] = {};
#pragma unroll
    for (int di = 0; di < MAX_DEG; di++) {
        if (ids[di] > 0) {
            const float4* p = reinterpret_cast<const float4*>(
                g_eo1 + (size_t)(ids[di] - 1) * 256 + lane * 8);
            float4 x = p[0], y = p[1];
            float wg = wv[di] * inv;
            o[0] += wg * x.x; o[1] += wg * x.y; o[2] += wg * x.z; o[3] += wg * x.w;
            o[4] += wg * y.x; o[5] += wg * y.y; o[6] += wg * y.z; o[7] += wg * y.w;
        }
    }
    float* dst = g_no1 + (size_t)n * 256 + lane * 8;
    *reinterpret_cast<float4*>(dst) =
        make_float4(eluf(o[0]), eluf(o[1]), eluf(o[2]), eluf(o[3]));
    *reinterpret_cast<float4*>(dst + 4) =
        make_float4(eluf(o[4]), eluf(o[5]), eluf(o[6]), eluf(o[7]));
}

// ---------------- layer2 edge attention: warp per edge, dim 128 -----------------
__global__ __launch_bounds__(256)
void edge_attn2(const int* __restrict__ el, const float* __restrict__ a2o) {
    int e = blockIdx.x * 8 + (threadIdx.x >> 5);
    if (e >= N_EDGES_C) return;
    int lane = threadIdx.x & 31;
    float se = g_se2[e];
    int ids[MAX_ARITY];
    float s[MAX_ARITY];
#pragma unroll
    for (int ai = 0; ai < MAX_ARITY; ai++) ids[ai] = el[e * MAX_ARITY + ai];
#pragma unroll
    for (int ai = 0; ai < MAX_ARITY; ai++)
        s[ai] = (ids[ai] > 0) ? lreluf(se + g_pn2[ids[ai] - 1]) : -1e9f;
    float m = s[0];
#pragma unroll
    for (int ai = 1; ai < MAX_ARITY; ai++) m = fmaxf(m, s[ai]);
    float wv[MAX_ARITY], den = 0.f;
#pragma unroll
    for (int ai = 0; ai < MAX_ARITY; ai++) { wv[ai] = expf(s[ai] - m); den += wv[ai]; }
    float inv = 1.f / den;
    float o[4] = {};
#pragma unroll
    for (int ai = 0; ai < MAX_ARITY; ai++) {
        if (ids[ai] > 0) {
            float4 x = *reinterpret_cast<const float4*>(
                g_hn2 + (size_t)(ids[ai] - 1) * 128 + lane * 4);
            float wg = wv[ai] * inv;
            o[0] += wg * x.x; o[1] += wg * x.y; o[2] += wg * x.z; o[3] += wg * x.w;
        }
    }
    *reinterpret_cast<float4*>(g_eo2 + (size_t)e * 128 + lane * 4) =
        make_float4(o[0], o[1], o[2], o[3]);
    // epilogue: pe2[e] = edge_out . a2o[128:256]
    float pe = 0.f;
#pragma unroll
    for (int i = 0; i < 4; i++) pe += o[i] * a2o[128 + lane * 4 + i];
    pe = warp_sum(pe);
    if (lane == 0) g_pe2[e] = pe;
}

// ---------------- layer2 node attention: warp per node, dim 128 -----------------
__global__ __launch_bounds__(256)
void node_attn2(const int* __restrict__ nl) {
    int n = blockIdx.x * 8 + (threadIdx.x >> 5);
    if (n >= N_NODES_C) return;
    int lane = threadIdx.x & 31;
    float sn = g_sn2[n];
    int ids[MAX_DEG];
    float s[MAX_DEG];
#pragma unroll
    for (int di = 0; di < MAX_DEG; di++) ids[di] = nl[n * MAX_DEG + di];
#pragma unroll
    for (int di = 0; di < MAX_DEG; di++)
        s[di] = (ids[di] > 0) ? lreluf(sn + g_pe2[ids[di] - 1]) : -1e9f;
    float m = s[0];
#pragma unroll
    for (int di = 1; di < MAX_DEG; di++) m = fmaxf(m, s[di]);
    float wv[MAX_DEG], den = 0.f;
#pragma unroll
    for (int di = 0; di < MAX_DEG; di++) { wv[di] = expf(s[di] - m); den += wv[di]; }
    float inv = 1.f / den;
    float o[4] = {};
#pragma unroll
    for (int di = 0; di < MAX_DEG; di++) {
        if (ids[di] > 0) {
            float4 x = *reinterpret_cast<const float4*>(
                g_eo2 + (size_t)(ids[di] - 1) * 128 + lane * 4);
            float wg = wv[di] * inv;
            o[0] += wg * x.x; o[1] += wg * x.y; o[2] += wg * x.z; o[3] += wg * x.w;
        }
    }
    *reinterpret_cast<float4*>(g_no2 + (size_t)n * 128 + lane * 4) =
        make_float4(o[0], o[1], o[2], o[3]);
}

// ---------------- final batch gather (applies ELU to layer2 outputs) ------------
__global__ __launch_bounds__(128)
void gather_out(const int* __restrict__ bi, float* __restrict__ out) {
    int b = blockIdx.x;
    int t = threadIdx.x;
    __shared__ int ids[7];
    __shared__ int lastnz;
    if (t < 7) ids[t] = bi[b * 7 + t];
    __syncthreads();
    if (t == 0) {
        int ln = 0;
#pragma unroll
        for (int j = 1; j < 7; j++) if (ids[j] != 0) ln = j;
        lastnz = ln;
    }
    __syncthreads();
    int ln = lastnz;
    out[(size_t)b * 896 + t] = eluf(g_eo2[(size_t)(ids[0] - 1) * 128 + t]);
#pragma unroll
    for (int a = 1; a < 7; a++) {
        int nid = ids[a] - 1;
        if (nid < 0) nid += N_NODES_C;
        float g = eluf(g_no2[(size_t)nid * 128 + t]);
        out[(size_t)b * 896 + a * 128 + t] = (a <= ln) ? g : 1.0f;
    }
}

// ---------------- launch ----------------
extern "C" void kernel_launch(void* const* d_in, const int* in_sizes, int n_in,
                              void* d_out, int out_size) {
    (void)in_sizes; (void)n_in; (void)out_size;
    const int*   bi    = (const int*)d_in[0];
    const int*   el    = (const int*)d_in[1];
    const int*   nl    = (const int*)d_in[2];
    const float* nemb  = (const float*)d_in[3];
    const float* eemb  = (const float*)d_in[4];
    const float* Wn    = (const float*)d_in[5];
    const float* We    = (const float*)d_in[6];
    const float* a1    = (const float*)d_in[7];
    const float* a2    = (const float*)d_in[8];
    const float* Wn_o  = (const float*)d_in[9];
    const float* We_o  = (const float*)d_in[10];
    const float* a1_o  = (const float*)d_in[11];
    const float* a2_o  = (const float*)d_in[12];
    float* out = (float*)d_out;

    float *hn1, *he1, *eo1, *no1, *hn2, *he2, *wnc, *wec;
    float *pn1, *sn1, *se1, *pn2, *sn2, *se2;
    cudaGetSymbolAddress((void**)&hn1, g_hn1);
    cudaGetSymbolAddress((void**)&he1, g_he1);
    cudaGetSymbolAddress((void**)&eo1, g_eo1);
    cudaGetSymbolAddress((void**)&no1, g_no1);
    cudaGetSymbolAddress((void**)&hn2, g_hn2);
    cudaGetSymbolAddress((void**)&he2, g_he2);
    cudaGetSymbolAddress((void**)&wnc, g_WnCat);
    cudaGetSymbolAddress((void**)&wec, g_WeCat);
    cudaGetSymbolAddress((void**)&pn1, g_pn1);
    cudaGetSymbolAddress((void**)&sn1, g_sn1);
    cudaGetSymbolAddress((void**)&se1, g_se1);
    cudaGetSymbolAddress((void**)&pn2, g_pn2);
    cudaGetSymbolAddress((void**)&sn2, g_sn2);
    cudaGetSymbolAddress((void**)&se2, g_se2);

    repack_w<<<128, 256>>>(Wn, We);

    // layer1 projections (tensor-core TF32; heads packed into N=256)
    gemm_tc<false><<<dim3(391, 4), 256>>>(nemb, wnc, hn1, N_NODES_C, 256, 128);
    gemm_tc<false><<<dim3(196, 4), 256>>>(eemb, wec, he1, N_EDGES_C, 256, 128);

    // scalar scores for layer1
    scal64<<<6250, 256>>>(hn1, N_NODES_C, a1, 64, pn1, a2, 0, sn1);
    scal64<<<3125, 256>>>(he1, N_EDGES_C, a1, 0, se1, (const float*)nullptr, 0, (float*)nullptr);

    edge_attn1<<<3125, 256>>>(el, a2);
    node_attn1<<<6250, 256>>>(nl);

    // layer2 projections (edge input gets ELU applied on the fly)
    gemm_tc<false><<<dim3(391, 2), 256>>>(no1, Wn_o, hn2, N_NODES_C, 128, 256);
    gemm_tc<true ><<<dim3(196, 2), 256>>>(eo1, We_o, he2, N_EDGES_C, 128, 256);

    // scalar scores for layer2
    scal128<<<6250, 256>>>(hn2, N_NODES_C, a1_o, 128, pn2, a2_o, 0, sn2);
    scal128<<<3125, 256>>>(he2, N_EDGES_C, a1_o, 0, se2, (const float*)nullptr, 0, (float*)nullptr);

    edge_attn2<<<3125, 256>>>(el, a1_o);
    node_attn2<<<6250, 256>>>(nl);

    gather_out<<<BATCH_C, 128>>>(bi, out);
}

// round 3
// speedup vs baseline: 1.9559x; 1.1994x over previous
#include <cuda_runtime.h>
#include <cstdint>

#define N_NODES_C 50000
#define N_EDGES_C 25000
#define MAX_ARITY 6
#define MAX_DEG 8
#define BATCH_C 4096

// ---------------- scratch (device globals; no allocations allowed) ----------------
__device__ __align__(256) float g_hn1[N_NODES_C * 256];   // layer1 node proj, [n][h*64+j]
__device__ __align__(256) float g_he1[N_EDGES_C * 256];   // layer1 edge proj
__device__ __align__(256) float g_eo1[N_EDGES_C * 256];   // layer1 edge_out (raw)
__device__ __align__(256) float g_no1[N_NODES_C * 256];   // layer1 node_out (ELU applied)
__device__ __align__(256) float g_hn2[N_NODES_C * 128];
__device__ __align__(256) float g_he2[N_EDGES_C * 128];
__device__ __align__(256) float g_eo2[N_EDGES_C * 128];   // layer2 edge_out (raw)
__device__ __align__(256) float g_no2[N_NODES_C * 128];   // layer2 node_out (raw)
__device__ __align__(256) float g_WnCat[128 * 256];       // Wn repacked [k][h*64+j]
__device__ __align__(256) float g_WeCat[128 * 256];
// score-weight vectors (column-indexed, filled by repack_w)
__device__ float g_wpn1[256];   // c=h*64+j -> a1[h*128+64+j]
__device__ float g_wqn1[256];   // c -> a2[h*128+j]
__device__ float g_wpe1[256];   // c -> a1[h*128+j]
__device__ float g_wpn2[128];   // c -> a1_o[128+c]
__device__ float g_wqn2[128];   // c -> a2_o[c]
__device__ float g_wpe2[128];   // c -> a1_o[c]
// scalar score caches
__device__ float g_pn1[N_NODES_C * 4];   // hn1 . a1[h, 64:128]
__device__ float g_sn1[N_NODES_C * 4];   // hn1 . a2[h, 0:64]
__device__ float g_se1[N_EDGES_C * 4];   // he1 . a1[h, 0:64]
__device__ float g_pe1[N_EDGES_C * 4];   // eo1 . a2[h, 64:128]
__device__ float g_pn2[N_NODES_C];       // hn2 . a1o[128:256]
__device__ float g_sn2[N_NODES_C];       // hn2 . a2o[0:128]
__device__ float g_se2[N_EDGES_C];       // he2 . a1o[0:128]
__device__ float g_pe2[N_EDGES_C];       // eo2 . a2o[128:256]

// ---------------- helpers ----------------
__device__ __forceinline__ float warp_sum(float v) {
#pragma unroll
    for (int o = 16; o > 0; o >>= 1) v += __shfl_xor_sync(0xffffffffu, v, o);
    return v;
}
__device__ __forceinline__ float seg8_sum(float v) {
#pragma unroll
    for (int o = 4; o > 0; o >>= 1) v += __shfl_xor_sync(0xffffffffu, v, o);
    return v;
}
__device__ __forceinline__ float eluf(float x)  { return x > 0.f ? x : expm1f(x); }
__device__ __forceinline__ float lreluf(float x){ return x > 0.f ? x : 0.2f * x; }
__device__ __forceinline__ unsigned f2tf(float x) {
    unsigned r; asm("cvt.rna.tf32.f32 %0, %1;" : "=r"(r) : "f"(x)); return r;
}
__device__ __forceinline__ void mma8(float c[4], unsigned a0, unsigned a1, unsigned a2,
                                     unsigned a3, unsigned b0, unsigned b1) {
    asm volatile(
        "mma.sync.aligned.m16n8k8.row.col.f32.tf32.tf32.f32 "
        "{%0,%1,%2,%3},{%4,%5,%6,%7},{%8,%9},{%0,%1,%2,%3};"
        : "+f"(c[0]), "+f"(c[1]), "+f"(c[2]), "+f"(c[3])
        : "r"(a0), "r"(a1), "r"(a2), "r"(a3), "r"(b0), "r"(b1));
}

// ---------------- zero score accumulators ----------------
__global__ void zero_scores() {
    int i = blockIdx.x * 256 + threadIdx.x;
    if (i < N_NODES_C * 4) { g_pn1[i] = 0.f; g_sn1[i] = 0.f; }
    if (i < N_EDGES_C * 4) g_se1[i] = 0.f;
    if (i < N_NODES_C)     { g_pn2[i] = 0.f; g_sn2[i] = 0.f; }
    if (i < N_EDGES_C)     g_se2[i] = 0.f;
}

// ---------------- weight repack ----------------
__global__ void repack_w(const float* __restrict__ Wn, const float* __restrict__ We,
                         const float* __restrict__ a1, const float* __restrict__ a2,
                         const float* __restrict__ a1o, const float* __restrict__ a2o) {
    int i = blockIdx.x * 256 + threadIdx.x;
    if (i < 4 * 128 * 64) {
        int h = i >> 13;
        int r = i & 8191;
        int k = r >> 6, j = r & 63;
        int o = k * 256 + h * 64 + j;
        g_WnCat[o] = Wn[i];
        g_WeCat[o] = We[i];
    }
    if (i < 256) {
        int h = i >> 6, j = i & 63;
        g_wpn1[i] = a1[h * 128 + 64 + j];
        g_wqn1[i] = a2[h * 128 + j];
        g_wpe1[i] = a1[h * 128 + j];
    }
    if (i < 128) {
        g_wpn2[i] = a1o[128 + i];
        g_wqn2[i] = a2o[i];
        g_wpe2[i] = a1o[i];
    }
}

// ---------------- TF32 tensor-core GEMM with fused score epilogue ----------------
// C[M,N] = act(A)[M,K] @ B[K,N]; optionally P[r*PS+pidx] += C_row . wp, same for Q.
// BM=128, BN=64, BK=16, 256 threads = 8 warps (4m x 2n), warp tile 32x32,
// double-buffered smem.
template <bool ELU_A, int SCORES>
__global__ __launch_bounds__(256)
void gemm_tc(const float* __restrict__ A, const float* __restrict__ B,
             float* __restrict__ C, int M, int N, int K,
             const float* __restrict__ wp, const float* __restrict__ wq,
             float* __restrict__ P, float* __restrict__ Q, int PS) {
    __shared__ unsigned As[2][128][20];
    __shared__ unsigned Bs[2][16][72];
    const int tid = threadIdx.x;
    const int bm = blockIdx.x * 128, bn = blockIdx.y * 64;
    const int w = tid >> 5, lane = tid & 31;
    const int wm = (w >> 1) * 32, wn = (w & 1) * 32;
    const int gid = lane >> 2, tig = lane & 3;
    const int arow = tid >> 1, acg = (tid & 1) * 8;
    const int brow = tid >> 4, bcol = (tid & 15) * 4;
    const bool aval = (bm + arow) < M;
    const float* Ap = A + (size_t)(bm + arow) * K;
    float acc[2][4][4] = {};

    auto stage = [&](int buf, float4 v0, float4 v1, float4 bv) {
        if (ELU_A) {
            v0.x = eluf(v0.x); v0.y = eluf(v0.y); v0.z = eluf(v0.z); v0.w = eluf(v0.w);
            v1.x = eluf(v1.x); v1.y = eluf(v1.y); v1.z = eluf(v1.z); v1.w = eluf(v1.w);
        }
        As[buf][arow][acg + 0] = f2tf(v0.x); As[buf][arow][acg + 1] = f2tf(v0.y);
        As[buf][arow][acg + 2] = f2tf(v0.z); As[buf][arow][acg + 3] = f2tf(v0.w);
        As[buf][arow][acg + 4] = f2tf(v1.x); As[buf][arow][acg + 5] = f2tf(v1.y);
        As[buf][arow][acg + 6] = f2tf(v1.z); As[buf][arow][acg + 7] = f2tf(v1.w);
        Bs[buf][brow][bcol + 0] = f2tf(bv.x); Bs[buf][brow][bcol + 1] = f2tf(bv.y);
        Bs[buf][brow][bcol + 2] = f2tf(bv.z); Bs[buf][brow][bcol + 3] = f2tf(bv.w);
    };

    const int T = K >> 4;
    {   // prologue: tile 0
        float4 v0 = make_float4(0.f, 0.f, 0.f, 0.f), v1 = v0;
        if (aval) {
            v0 = *reinterpret_cast<const float4*>(Ap + acg);
            v1 = *reinterpret_cast<const float4*>(Ap + acg + 4);
        }
        float4 bv = *reinterpret_cast<const float4*>(B + (size_t)brow * N + bn + bcol);
        stage(0, v0, v1, bv);
    }
    __syncthreads();

    for (int it = 0; it < T; it++) {
        const int buf = it & 1;
        const bool more = (it + 1) < T;
        float4 n0 = make_float4(0.f, 0.f, 0.f, 0.f), n1 = n0, nb = n0;
        if (more) {
            int k0 = (it + 1) << 4;
            if (aval) {
                n0 = *reinterpret_cast<const float4*>(Ap + k0 + acg);
                n1 = *reinterpret_cast<const float4*>(Ap + k0 + acg + 4);
            }
            nb = *reinterpret_cast<const float4*>(B + (size_t)(k0 + brow) * N + bn + bcol);
        }
#pragma unroll
        for (int kk = 0; kk < 16; kk += 8) {
            unsigned af[2][4], bf[4][2];
#pragma unroll
            for (int mt = 0; mt < 2; mt++) {
                int m0 = wm + mt * 16;
                af[mt][0] = As[buf][m0 + gid][kk + tig];
                af[mt][1] = As[buf][m0 + gid + 8][kk + tig];
                af[mt][2] = As[buf][m0 + gid][kk + tig + 4];
                af[mt][3] = As[buf][m0 + gid + 8][kk + tig + 4];
            }
#pragma unroll
            for (int nt = 0; nt < 4; nt++) {
                int n0i = wn + nt * 8;
                bf[nt][0] = Bs[buf][kk + tig][n0i + gid];
                bf[nt][1] = Bs[buf][kk + tig + 4][n0i + gid];
            }
#pragma unroll
            for (int mt = 0; mt < 2; mt++)
#pragma unroll
                for (int nt = 0; nt < 4; nt++)
                    mma8(acc[mt][nt], af[mt][0], af[mt][1], af[mt][2], af[mt][3],
                         bf[nt][0], bf[nt][1]);
        }
        if (more) stage(buf ^ 1, n0, n1, nb);
        __syncthreads();
    }

    // C write
#pragma unroll
    for (int mt = 0; mt < 2; mt++) {
#pragma unroll
        for (int nt = 0; nt < 4; nt++) {
            int r0 = bm + wm + mt * 16 + gid;
            int c = bn + wn + nt * 8 + tig * 2;
            if (r0 < M)
                *reinterpret_cast<float2*>(C + (size_t)r0 * N + c) =
                    make_float2(acc[mt][nt][0], acc[mt][nt][1]);
            int r1 = r0 + 8;
            if (r1 < M)
                *reinterpret_cast<float2*>(C + (size_t)r1 * N + c) =
                    make_float2(acc[mt][nt][2], acc[mt][nt][3]);
        }
    }

    // fused score epilogue
    if (SCORES >= 1) {
        const int pidx = (PS == 4) ? blockIdx.y : 0;
        float wpv[4][2], wqv[4][2];
#pragma unroll
        for (int nt = 0; nt < 4; nt++) {
            int c = bn + wn + nt * 8 + tig * 2;
            wpv[nt][0] = wp[c]; wpv[nt][1] = wp[c + 1];
            if (SCORES == 2) { wqv[nt][0] = wq[c]; wqv[nt][1] = wq[c + 1]; }
        }
#pragma unroll
        for (int mt = 0; mt < 2; mt++) {
#pragma unroll
            for (int half = 0; half < 2; half++) {
                float p = 0.f, q = 0.f;
#pragma unroll
                for (int nt = 0; nt < 4; nt++) {
                    p += acc[mt][nt][half * 2 + 0] * wpv[nt][0]
                       + acc[mt][nt][half * 2 + 1] * wpv[nt][1];
                    if (SCORES == 2)
                        q += acc[mt][nt][half * 2 + 0] * wqv[nt][0]
                           + acc[mt][nt][half * 2 + 1] * wqv[nt][1];
                }
                p += __shfl_xor_sync(0xffffffffu, p, 1);
                p += __shfl_xor_sync(0xffffffffu, p, 2);
                if (SCORES == 2) {
                    q += __shfl_xor_sync(0xffffffffu, q, 1);
                    q += __shfl_xor_sync(0xffffffffu, q, 2);
                }
                int r = bm + wm + mt * 16 + gid + half * 8;
                if (tig == 0 && r < M) {
                    atomicAdd(&P[(size_t)r * PS + pidx], p);
                    if (SCORES == 2) atomicAdd(&Q[(size_t)r * PS + pidx], q);
                }
            }
        }
    }
}

// ---------------- layer1 edge attention: warp per edge, all 4 heads -------------
__global__ __launch_bounds__(256)
void edge_attn1(const int* __restrict__ el, const float* __restrict__ a2) {
    int e = blockIdx.x * 8 + (threadIdx.x >> 5);
    if (e >= N_EDGES_C) return;
    int lane = threadIdx.x & 31;
    int h = lane >> 3, jl = lane & 7;
    float se = g_se1[e * 4 + h];
    int ids[MAX_ARITY];
    float s[MAX_ARITY];
#pragma unroll
    for (int ai = 0; ai < MAX_ARITY; ai++) ids[ai] = el[e * MAX_ARITY + ai];
#pragma unroll
    for (int ai = 0; ai < MAX_ARITY; ai++)
        s[ai] = (ids[ai] > 0) ? lreluf(se + g_pn1[(ids[ai] - 1) * 4 + h]) : -1e9f;
    float m = s[0];
#pragma unroll
    for (int ai = 1; ai < MAX_ARITY; ai++) m = fmaxf(m, s[ai]);
    float wv[MAX_ARITY], den = 0.f;
#pragma unroll
    for (int ai = 0; ai < MAX_ARITY; ai++) { wv[ai] = expf(s[ai] - m); den += wv[ai]; }
    float inv = 1.f / den;
    float o[8] = {};
#pragma unroll
    for (int ai = 0; ai < MAX_ARITY; ai++) {
        if (ids[ai] > 0) {
            const float4* p = reinterpret_cast<const float4*>(
                g_hn1 + (size_t)(ids[ai] - 1) * 256 + lane * 8);
            float4 x = p[0], y = p[1];
            float wg = wv[ai] * inv;
            o[0] += wg * x.x; o[1] += wg * x.y; o[2] += wg * x.z; o[3] += wg * x.w;
            o[4] += wg * y.x; o[5] += wg * y.y; o[6] += wg * y.z; o[7] += wg * y.w;
        }
    }
    float* dst = g_eo1 + (size_t)e * 256 + lane * 8;
    *reinterpret_cast<float4*>(dst)     = make_float4(o[0], o[1], o[2], o[3]);
    *reinterpret_cast<float4*>(dst + 4) = make_float4(o[4], o[5], o[6], o[7]);
    // epilogue: pe1[e,h] = edge_out . a2[h, 64:128]
    float pe = 0.f;
#pragma unroll
    for (int i = 0; i < 8; i++) pe += o[i] * a2[h * 128 + 64 + jl * 8 + i];
    pe = seg8_sum(pe);
    if (jl == 0) g_pe1[e * 4 + h] = pe;
}

// ---------------- layer1 node attention: warp per node, +ELU --------------------
__global__ __launch_bounds__(256)
void node_attn1(const int* __restrict__ nl) {
    int n = blockIdx.x * 8 + (threadIdx.x >> 5);
    if (n >= N_NODES_C) return;
    int lane = threadIdx.x & 31;
    int h = lane >> 3;
    float sn = g_sn1[n * 4 + h];
    int ids[MAX_DEG];
    float s[MAX_DEG];
#pragma unroll
    for (int di = 0; di < MAX_DEG; di++) ids[di] = nl[n * MAX_DEG + di];
#pragma unroll
    for (int di = 0; di < MAX_DEG; di++)
        s[di] = (ids[di] > 0) ? lreluf(sn + g_pe1[(ids[di] - 1) * 4 + h]) : -1e9f;
    float m = s[0];
#pragma unroll
    for (int di = 1; di < MAX_DEG; di++) m = fmaxf(m, s[di]);
    float wv[MAX_DEG], den = 0.f;
#pragma unroll
    for (int di = 0; di < MAX_DEG; di++) { wv[di] = expf(s[di] - m); den += wv[di]; }
    float inv = 1.f / den;
    float o[8] = {};
#pragma unroll
    for (int di = 0; di < MAX_DEG; di++) {
        if (ids[di] > 0) {
            const float4* p = reinterpret_cast<const float4*>(
                g_eo1 + (size_t)(ids[di] - 1) * 256 + lane * 8);
            float4 x = p[0], y = p[1];
            float wg = wv[di] * inv;
            o[0] += wg * x.x; o[1] += wg * x.y; o[2] += wg * x.z; o[3] += wg * x.w;
            o[4] += wg * y.x; o[5] += wg * y.y; o[6] += wg * y.z; o[7] += wg * y.w;
        }
    }
    float* dst = g_no1 + (size_t)n * 256 + lane * 8;
    *reinterpret_cast<float4*>(dst) =
        make_float4(eluf(o[0]), eluf(o[1]), eluf(o[2]), eluf(o[3]));
    *reinterpret_cast<float4*>(dst + 4) =
        make_float4(eluf(o[4]), eluf(o[5]), eluf(o[6]), eluf(o[7]));
}

// ---------------- layer2 edge attention: warp per edge, dim 128 -----------------
__global__ __launch_bounds__(256)
void edge_attn2(const int* __restrict__ el, const float* __restrict__ a2o) {
    int e = blockIdx.x * 8 + (threadIdx.x >> 5);
    if (e >= N_EDGES_C) return;
    int lane = threadIdx.x & 31;
    float se = g_se2[e];
    int ids[MAX_ARITY];
    float s[MAX_ARITY];
#pragma unroll
    for (int ai = 0; ai < MAX_ARITY; ai++) ids[ai] = el[e * MAX_ARITY + ai];
#pragma unroll
    for (int ai = 0; ai < MAX_ARITY; ai++)
        s[ai] = (ids[ai] > 0) ? lreluf(se + g_pn2[ids[ai] - 1]) : -1e9f;
    float m = s[0];
#pragma unroll
    for (int ai = 1; ai < MAX_ARITY; ai++) m = fmaxf(m, s[ai]);
    float wv[MAX_ARITY], den = 0.f;
#pragma unroll
    for (int ai = 0; ai < MAX_ARITY; ai++) { wv[ai] = expf(s[ai] - m); den += wv[ai]; }
    float inv = 1.f / den;
    float o[4] = {};
#pragma unroll
    for (int ai = 0; ai < MAX_ARITY; ai++) {
        if (ids[ai] > 0) {
            float4 x = *reinterpret_cast<const float4*>(
                g_hn2 + (size_t)(ids[ai] - 1) * 128 + lane * 4);
            float wg = wv[ai] * inv;
            o[0] += wg * x.x; o[1] += wg * x.y; o[2] += wg * x.z; o[3] += wg * x.w;
        }
    }
    *reinterpret_cast<float4*>(g_eo2 + (size_t)e * 128 + lane * 4) =
        make_float4(o[0], o[1], o[2], o[3]);
    // epilogue: pe2[e] = edge_out . a2o[128:256]
    float pe = 0.f;
#pragma unroll
    for (int i = 0; i < 4; i++) pe += o[i] * a2o[128 + lane * 4 + i];
    pe = warp_sum(pe);
    if (lane == 0) g_pe2[e] = pe;
}

// ---------------- layer2 node attention: warp per node, dim 128 -----------------
__global__ __launch_bounds__(256)
void node_attn2(const int* __restrict__ nl) {
    int n = blockIdx.x * 8 + (threadIdx.x >> 5);
    if (n >= N_NODES_C) return;
    int lane = threadIdx.x & 31;
    float sn = g_sn2[n];
    int ids[MAX_DEG];
    float s[MAX_DEG];
#pragma unroll
    for (int di = 0; di < MAX_DEG; di++) ids[di] = nl[n * MAX_DEG + di];
#pragma unroll
    for (int di = 0; di < MAX_DEG; di++)
        s[di] = (ids[di] > 0) ? lreluf(sn + g_pe2[ids[di] - 1]) : -1e9f;
    float m = s[0];
#pragma unroll
    for (int di = 1; di < MAX_DEG; di++) m = fmaxf(m, s[di]);
    float wv[MAX_DEG], den = 0.f;
#pragma unroll
    for (int di = 0; di < MAX_DEG; di++) { wv[di] = expf(s[di] - m); den += wv[di]; }
    float inv = 1.f / den;
    float o[4] = {};
#pragma unroll
    for (int di = 0; di < MAX_DEG; di++) {
        if (ids[di] > 0) {
            float4 x = *reinterpret_cast<const float4*>(
                g_eo2 + (size_t)(ids[di] - 1) * 128 + lane * 4);
            float wg = wv[di] * inv;
            o[0] += wg * x.x; o[1] += wg * x.y; o[2] += wg * x.z; o[3] += wg * x.w;
        }
    }
    *reinterpret_cast<float4*>(g_no2 + (size_t)n * 128 + lane * 4) =
        make_float4(o[0], o[1], o[2], o[3]);
}

// ---------------- final batch gather (applies ELU to layer2 outputs) ------------
__global__ __launch_bounds__(128)
void gather_out(const int* __restrict__ bi, float* __restrict__ out) {
    int b = blockIdx.x;
    int t = threadIdx.x;
    __shared__ int ids[7];
    __shared__ int lastnz;
    if (t < 7) ids[t] = bi[b * 7 + t];
    __syncthreads();
    if (t == 0) {
        int ln = 0;
#pragma unroll
        for (int j = 1; j < 7; j++) if (ids[j] != 0) ln = j;
        lastnz = ln;
    }
    __syncthreads();
    int ln = lastnz;
    out[(size_t)b * 896 + t] = eluf(g_eo2[(size_t)(ids[0] - 1) * 128 + t]);
#pragma unroll
    for (int a = 1; a < 7; a++) {
        int nid = ids[a] - 1;
        if (nid < 0) nid += N_NODES_C;
        float g = eluf(g_no2[(size_t)nid * 128 + t]);
        out[(size_t)b * 896 + a * 128 + t] = (a <= ln) ? g : 1.0f;
    }
}

// ---------------- launch ----------------
extern "C" void kernel_launch(void* const* d_in, const int* in_sizes, int n_in,
                              void* d_out, int out_size) {
    (void)in_sizes; (void)n_in; (void)out_size;
    const int*   bi    = (const int*)d_in[0];
    const int*   el    = (const int*)d_in[1];
    const int*   nl    = (const int*)d_in[2];
    const float* nemb  = (const float*)d_in[3];
    const float* eemb  = (const float*)d_in[4];
    const float* Wn    = (const float*)d_in[5];
    const float* We    = (const float*)d_in[6];
    const float* a1    = (const float*)d_in[7];
    const float* a2    = (const float*)d_in[8];
    const float* Wn_o  = (const float*)d_in[9];
    const float* We_o  = (const float*)d_in[10];
    const float* a1_o  = (const float*)d_in[11];
    const float* a2_o  = (const float*)d_in[12];
    float* out = (float*)d_out;

    float *hn1, *he1, *eo1, *no1, *hn2, *he2, *wnc, *wec;
    float *pn1, *sn1, *se1, *pn2, *sn2, *se2;
    float *wpn1, *wqn1, *wpe1, *wpn2, *wqn2, *wpe2;
    cudaGetSymbolAddress((void**)&hn1, g_hn1);
    cudaGetSymbolAddress((void**)&he1, g_he1);
    cudaGetSymbolAddress((void**)&eo1, g_eo1);
    cudaGetSymbolAddress((void**)&no1, g_no1);
    cudaGetSymbolAddress((void**)&hn2, g_hn2);
    cudaGetSymbolAddress((void**)&he2, g_he2);
    cudaGetSymbolAddress((void**)&wnc, g_WnCat);
    cudaGetSymbolAddress((void**)&wec, g_WeCat);
    cudaGetSymbolAddress((void**)&pn1, g_pn1);
    cudaGetSymbolAddress((void**)&sn1, g_sn1);
    cudaGetSymbolAddress((void**)&se1, g_se1);
    cudaGetSymbolAddress((void**)&pn2, g_pn2);
    cudaGetSymbolAddress((void**)&sn2, g_sn2);
    cudaGetSymbolAddress((void**)&se2, g_se2);
    cudaGetSymbolAddress((void**)&wpn1, g_wpn1);
    cudaGetSymbolAddress((void**)&wqn1, g_wqn1);
    cudaGetSymbolAddress((void**)&wpe1, g_wpe1);
    cudaGetSymbolAddress((void**)&wpn2, g_wpn2);
    cudaGetSymbolAddress((void**)&wqn2, g_wqn2);
    cudaGetSymbolAddress((void**)&wpe2, g_wpe2);

    zero_scores<<<782, 256>>>();
    repack_w<<<128, 256>>>(Wn, We, a1, a2, a1_o, a2_o);

    // layer1 projections + fused scores
    gemm_tc<false, 2><<<dim3(391, 4), 256>>>(nemb, wnc, hn1, N_NODES_C, 256, 128,
                                             wpn1, wqn1, pn1, sn1, 4);
    gemm_tc<false, 1><<<dim3(196, 4), 256>>>(eemb, wec, he1, N_EDGES_C, 256, 128,
                                             wpe1, nullptr, se1, nullptr, 4);

    edge_attn1<<<3125, 256>>>(el, a2);
    node_attn1<<<6250, 256>>>(nl);

    // layer2 projections + fused scores (edge input gets ELU on the fly)
    gemm_tc<false, 2><<<dim3(391, 2), 256>>>(no1, Wn_o, hn2, N_NODES_C, 128, 256,
                                             wpn2, wqn2, pn2, sn2, 1);
    gemm_tc<true, 1><<<dim3(196, 2), 256>>>(eo1, We_o, he2, N_EDGES_C, 128, 256,
                                            wpe2, nullptr, se2, nullptr, 1);

    edge_attn2<<<3125, 256>>>(el, a1_o);
    node_attn2<<<6250, 256>>>(nl);

    gather_out<<<BATCH_C, 128>>>(bi, out);
}

// round 4
// speedup vs baseline: 2.2609x; 1.1559x over previous
#include <cuda_runtime.h>
#include <cuda_bf16.h>
#include <cstdint>

#define N_NODES_C 50000
#define N_EDGES_C 25000
#define MAX_ARITY 6
#define MAX_DEG 8
#define BATCH_C 4096

// ---------------- scratch (device globals; no allocations allowed) ----------------
__device__ __align__(256) float g_hn1[N_NODES_C * 256];
__device__ __align__(256) float g_he1[N_EDGES_C * 256];
__device__ __align__(256) float g_eo1[N_EDGES_C * 256];
__device__ __align__(256) float g_no1[N_NODES_C * 256];
__device__ __align__(256) float g_hn2[N_NODES_C * 128];
__device__ __align__(256) float g_he2[N_EDGES_C * 128];
__device__ __align__(256) float g_eo2[N_EDGES_C * 128];
__device__ __align__(256) float g_no2[N_NODES_C * 128];
// pre-transposed bf16 weights, [n][k]
__device__ __align__(256) __nv_bfloat16 g_Bt1n[256 * 128];
__device__ __align__(256) __nv_bfloat16 g_Bt1e[256 * 128];
__device__ __align__(256) __nv_bfloat16 g_Bt2n[128 * 256];
__device__ __align__(256) __nv_bfloat16 g_Bt2e[128 * 256];
// score-weight vectors (column-indexed)
__device__ float g_wpn1[256];
__device__ float g_wqn1[256];
__device__ float g_wpe1[256];
__device__ float g_wpn2[128];
__device__ float g_wqn2[128];
__device__ float g_wpe2[128];
// scalar score caches
__device__ float g_pn1[N_NODES_C * 4];
__device__ float g_sn1[N_NODES_C * 4];
__device__ float g_se1[N_EDGES_C * 4];
__device__ float g_pe1[N_EDGES_C * 4];
__device__ float g_pn2[N_NODES_C];
__device__ float g_sn2[N_NODES_C];
__device__ float g_se2[N_EDGES_C];
__device__ float g_pe2[N_EDGES_C];

// ---------------- helpers ----------------
__device__ __forceinline__ float warp_sum(float v) {
#pragma unroll
    for (int o = 16; o > 0; o >>= 1) v += __shfl_xor_sync(0xffffffffu, v, o);
    return v;
}
__device__ __forceinline__ float seg8_sum(float v) {
#pragma unroll
    for (int o = 4; o > 0; o >>= 1) v += __shfl_xor_sync(0xffffffffu, v, o);
    return v;
}
__device__ __forceinline__ float eluf(float x)  { return x > 0.f ? x : expm1f(x); }
__device__ __forceinline__ float lreluf(float x){ return x > 0.f ? x : 0.2f * x; }

__device__ __forceinline__ void ldsm4(unsigned r[4], unsigned addr) {
    asm volatile("ldmatrix.sync.aligned.m8n8.x4.shared.b16 {%0,%1,%2,%3},[%4];"
                 : "=r"(r[0]), "=r"(r[1]), "=r"(r[2]), "=r"(r[3]) : "r"(addr));
}
__device__ __forceinline__ void mma16(float c[4], const unsigned a[4],
                                      unsigned b0, unsigned b1) {
    asm volatile(
        "mma.sync.aligned.m16n8k16.row.col.f32.bf16.bf16.f32 "
        "{%0,%1,%2,%3},{%4,%5,%6,%7},{%8,%9},{%0,%1,%2,%3};"
        : "+f"(c[0]), "+f"(c[1]), "+f"(c[2]), "+f"(c[3])
        : "r"(a[0]), "r"(a[1]), "r"(a[2]), "r"(a[3]), "r"(b0), "r"(b1));
}
#define CP_ASYNC16(dst, src) \
    asm volatile("cp.async.ca.shared.global [%0], [%1], 16;" :: "r"(dst), "l"(src))
#define CP_COMMIT  asm volatile("cp.async.commit_group;" ::: "memory")
#define CP_WAIT0   asm volatile("cp.async.wait_group 0;" ::: "memory")

__device__ __forceinline__ unsigned packbf(float a, float b) {
    __nv_bfloat162 h = __floats2bfloat162_rn(a, b);
    return *reinterpret_cast<unsigned*>(&h);
}

// ---------------- prep: zero scores, transpose+convert weights, score vectors ----
__global__ void prep(const float* __restrict__ Wn, const float* __restrict__ We,
                     const float* __restrict__ Wn_o, const float* __restrict__ We_o,
                     const float* __restrict__ a1, const float* __restrict__ a2,
                     const float* __restrict__ a1o, const float* __restrict__ a2o) {
    int i = blockIdx.x * 256 + threadIdx.x;
    if (i < 32768) {
        // layer1: Bt[c][k], c = h*64+j, value Wn[h][k][j]
        int c = i >> 7, k = i & 127;
        int h = c >> 6, j = c & 63;
        g_Bt1n[i] = __float2bfloat16_rn(Wn[h * 8192 + k * 64 + j]);
        g_Bt1e[i] = __float2bfloat16_rn(We[h * 8192 + k * 64 + j]);
        // layer2: Bt[n][k] = W_o[k][n]
        int n2 = i >> 8, k2 = i & 255;
        g_Bt2n[i] = __float2bfloat16_rn(Wn_o[k2 * 128 + n2]);
        g_Bt2e[i] = __float2bfloat16_rn(We_o[k2 * 128 + n2]);
    }
    if (i < 256) {
        int h = i >> 6, j = i & 63;
        g_wpn1[i] = a1[h * 128 + 64 + j];
        g_wqn1[i] = a2[h * 128 + j];
        g_wpe1[i] = a1[h * 128 + j];
    }
    if (i < 128) {
        g_wpn2[i] = a1o[128 + i];
        g_wqn2[i] = a2o[i];
        g_wpe2[i] = a1o[i];
    }
    if (i < N_NODES_C * 4) { g_pn1[i] = 0.f; g_sn1[i] = 0.f; }
    if (i < N_EDGES_C * 4) g_se1[i] = 0.f;
    if (i < N_NODES_C)     { g_pn2[i] = 0.f; g_sn2[i] = 0.f; }
    if (i < N_EDGES_C)     g_se2[i] = 0.f;
}

// ---------------- BF16 tensor-core GEMM + fused score epilogue -------------------
// C[M,N] = act(A)[M,K] @ Bt^T  (Bt is [n][k] bf16). BM=128, BN=64, BK=16,
// 256 threads = 8 warps (4m x 2n), warp tile 32x32, m16n8k16, ldmatrix frags,
// cp.async B staging, double-buffered.
template <bool ELU_A, int SCORES>
__global__ __launch_bounds__(256)
void gemm_tc(const float* __restrict__ A, const __nv_bfloat16* __restrict__ Bt,
             float* __restrict__ C, int M, int N, int K,
             const float* __restrict__ wp, const float* __restrict__ wq,
             float* __restrict__ P, float* __restrict__ Q, int PS) {
    __shared__ __align__(16) __nv_bfloat16 As[2][128][24];  // 48B row stride
    __shared__ __align__(16) __nv_bfloat16 Bs[2][64][24];
    const int tid = threadIdx.x;
    const int bm = blockIdx.x * 128, bn = blockIdx.y * 64;
    const int w = tid >> 5, lane = tid & 31;
    const int wm = (w >> 1) * 32, wn = (w & 1) * 32;
    const int gid = lane >> 2, tig = lane & 3;
    const int arow = tid >> 1, acg = (tid & 1) * 8;
    const bool aval = (bm + arow) < M;
    const float* Ap = A + (size_t)(bm + arow) * K;
    float acc[2][4][4] = {};

    const unsigned asBase = (unsigned)__cvta_generic_to_shared(&As[0][0][0]);
    const unsigned bsBase = (unsigned)__cvta_generic_to_shared(&Bs[0][0][0]);
    // per-lane ldmatrix offsets
    const unsigned aoffL = (unsigned)((wm + (lane & 15)) * 48 + (lane >> 4) * 16);
    const unsigned boffL = (unsigned)((wn + ((lane >> 4) << 3) + (lane & 7)) * 48
                                      + ((lane >> 3) & 1) * 16);
    // B staging (first 128 threads)
    const int brow = tid >> 1, bch = tid & 1;

    auto stageA = [&](int buf, float4 v0, float4 v1) {
        if (ELU_A) {
            v0.x = eluf(v0.x); v0.y = eluf(v0.y); v0.z = eluf(v0.z); v0.w = eluf(v0.w);
            v1.x = eluf(v1.x); v1.y = eluf(v1.y); v1.z = eluf(v1.z); v1.w = eluf(v1.w);
        }
        uint4 u;
        u.x = packbf(v0.x, v0.y); u.y = packbf(v0.z, v0.w);
        u.z = packbf(v1.x, v1.y); u.w = packbf(v1.z, v1.w);
        *reinterpret_cast<uint4*>(&As[buf][arow][acg]) = u;
    };

    const int T = K >> 4;
    {   // prologue: tile 0
        float4 v0 = make_float4(0.f, 0.f, 0.f, 0.f), v1 = v0;
        if (aval) {
            v0 = *reinterpret_cast<const float4*>(Ap + acg);
            v1 = *reinterpret_cast<const float4*>(Ap + acg + 4);
        }
        if (tid < 128) {
            unsigned dst = bsBase + (unsigned)(brow * 48 + bch * 16);
            CP_ASYNC16(dst, Bt + (size_t)(bn + brow) * K + bch * 8);
        }
        CP_COMMIT;
        stageA(0, v0, v1);
    }
    CP_WAIT0;
    __syncthreads();

    for (int it = 0; it < T; it++) {
        const int buf = it & 1;
        const bool more = (it + 1) < T;
        float4 v0 = make_float4(0.f, 0.f, 0.f, 0.f), v1 = v0;
        if (more) {
            int k0 = (it + 1) << 4;
            if (aval) {
                v0 = *reinterpret_cast<const float4*>(Ap + k0 + acg);
                v1 = *reinterpret_cast<const float4*>(Ap + k0 + acg + 4);
            }
            if (tid < 128) {
                unsigned dst = bsBase + (unsigned)((buf ^ 1) * 3072 + brow * 48 + bch * 16);
                CP_ASYNC16(dst, Bt + (size_t)(bn + brow) * K + k0 + bch * 8);
            }
        }
        CP_COMMIT;

        unsigned af[2][4], bfr[2][4];
        unsigned ab = asBase + (unsigned)(buf * 6144) + aoffL;
        ldsm4(af[0], ab);
        ldsm4(af[1], ab + 16 * 48);
        unsigned bb = bsBase + (unsigned)(buf * 3072) + boffL;
        ldsm4(bfr[0], bb);
        ldsm4(bfr[1], bb + 16 * 48);
#pragma unroll
        for (int mt = 0; mt < 2; mt++)
#pragma unroll
            for (int nt = 0; nt < 4; nt++)
                mma16(acc[mt][nt], af[mt],
                      bfr[nt >> 1][(nt & 1) * 2], bfr[nt >> 1][(nt & 1) * 2 + 1]);

        if (more) stageA(buf ^ 1, v0, v1);
        CP_WAIT0;
        __syncthreads();
    }

    // C write
#pragma unroll
    for (int mt = 0; mt < 2; mt++) {
#pragma unroll
        for (int nt = 0; nt < 4; nt++) {
            int r0 = bm + wm + mt * 16 + gid;
            int c = bn + wn + nt * 8 + tig * 2;
            if (r0 < M)
                *reinterpret_cast<float2*>(C + (size_t)r0 * N + c) =
                    make_float2(acc[mt][nt][0], acc[mt][nt][1]);
            int r1 = r0 + 8;
            if (r1 < M)
                *reinterpret_cast<float2*>(C + (size_t)r1 * N + c) =
                    make_float2(acc[mt][nt][2], acc[mt][nt][3]);
        }
    }

    // fused score epilogue
    if (SCORES >= 1) {
        const int pidx = (PS == 4) ? blockIdx.y : 0;
        float wpv[4][2], wqv[4][2];
#pragma unroll
        for (int nt = 0; nt < 4; nt++) {
            int c = bn + wn + nt * 8 + tig * 2;
            wpv[nt][0] = wp[c]; wpv[nt][1] = wp[c + 1];
            if (SCORES == 2) { wqv[nt][0] = wq[c]; wqv[nt][1] = wq[c + 1]; }
        }
#pragma unroll
        for (int mt = 0; mt < 2; mt++) {
#pragma unroll
            for (int half = 0; half < 2; half++) {
                float p = 0.f, q = 0.f;
#pragma unroll
                for (int nt = 0; nt < 4; nt++) {
                    p += acc[mt][nt][half * 2 + 0] * wpv[nt][0]
                       + acc[mt][nt][half * 2 + 1] * wpv[nt][1];
                    if (SCORES == 2)
                        q += acc[mt][nt][half * 2 + 0] * wqv[nt][0]
                           + acc[mt][nt][half * 2 + 1] * wqv[nt][1];
                }
                p += __shfl_xor_sync(0xffffffffu, p, 1);
                p += __shfl_xor_sync(0xffffffffu, p, 2);
                if (SCORES == 2) {
                    q += __shfl_xor_sync(0xffffffffu, q, 1);
                    q += __shfl_xor_sync(0xffffffffu, q, 2);
                }
                int r = bm + wm + mt * 16 + gid + half * 8;
                if (tig == 0 && r < M) {
                    atomicAdd(&P[(size_t)r * PS + pidx], p);
                    if (SCORES == 2) atomicAdd(&Q[(size_t)r * PS + pidx], q);
                }
            }
        }
    }
}

// ---------------- layer1 edge attention: warp per edge, all 4 heads -------------
__global__ __launch_bounds__(256)
void edge_attn1(const int* __restrict__ el, const float* __restrict__ a2) {
    int e = blockIdx.x * 8 + (threadIdx.x >> 5);
    if (e >= N_EDGES_C) return;
    int lane = threadIdx.x & 31;
    int h = lane >> 3, jl = lane & 7;
    float se = g_se1[e * 4 + h];
    int ids[MAX_ARITY];
    float s[MAX_ARITY];
#pragma unroll
    for (int ai = 0; ai < MAX_ARITY; ai++) ids[ai] = el[e * MAX_ARITY + ai];
#pragma unroll
    for (int ai = 0; ai < MAX_ARITY; ai++)
        s[ai] = (ids[ai] > 0) ? lreluf(se + g_pn1[(ids[ai] - 1) * 4 + h]) : -1e9f;
    float m = s[0];
#pragma unroll
    for (int ai = 1; ai < MAX_ARITY; ai++) m = fmaxf(m, s[ai]);
    float wv[MAX_ARITY], den = 0.f;
#pragma unroll
    for (int ai = 0; ai < MAX_ARITY; ai++) { wv[ai] = expf(s[ai] - m); den += wv[ai]; }
    float inv = 1.f / den;
    float o[8] = {};
#pragma unroll
    for (int ai = 0; ai < MAX_ARITY; ai++) {
        if (ids[ai] > 0) {
            const float4* p = reinterpret_cast<const float4*>(
                g_hn1 + (size_t)(ids[ai] - 1) * 256 + lane * 8);
            float4 x = p[0], y = p[1];
            float wg = wv[ai] * inv;
            o[0] += wg * x.x; o[1] += wg * x.y; o[2] += wg * x.z; o[3] += wg * x.w;
            o[4] += wg * y.x; o[5] += wg * y.y; o[6] += wg * y.z; o[7] += wg * y.w;
        }
    }
    float* dst = g_eo1 + (size_t)e * 256 + lane * 8;
    *reinterpret_cast<float4*>(dst)     = make_float4(o[0], o[1], o[2], o[3]);
    *reinterpret_cast<float4*>(dst + 4) = make_float4(o[4], o[5], o[6], o[7]);
    float pe = 0.f;
#pragma unroll
    for (int i = 0; i < 8; i++) pe += o[i] * a2[h * 128 + 64 + jl * 8 + i];
    pe = seg8_sum(pe);
    if (jl == 0) g_pe1[e * 4 + h] = pe;
}

// ---------------- layer1 node attention: warp per node, +ELU --------------------
__global__ __launch_bounds__(256)
void node_attn1(const int* __restrict__ nl) {
    int n = blockIdx.x * 8 + (threadIdx.x >> 5);
    if (n >= N_NODES_C) return;
    int lane = threadIdx.x & 31;
    int h = lane >> 3;
    float sn = g_sn1[n * 4 + h];
    int ids[MAX_DEG];
    float s[MAX_DEG];
#pragma unroll
    for (int di = 0; di < MAX_DEG; di++) ids[di] = nl[n * MAX_DEG + di];
#pragma unroll
    for (int di = 0; di < MAX_DEG; di++)
        s[di] = (ids[di] > 0) ? lreluf(sn + g_pe1[(ids[di] - 1) * 4 + h]) : -1e9f;
    float m = s[0];
#pragma unroll
    for (int di = 1; di < MAX_DEG; di++) m = fmaxf(m, s[di]);
    float wv[MAX_DEG], den = 0.f;
#pragma unroll
    for (int di = 0; di < MAX_DEG; di++) { wv[di] = expf(s[di] - m); den += wv[di]; }
    float inv = 1.f / den;
    float o[8] = {};
#pragma unroll
    for (int di = 0; di < MAX_DEG; di++) {
        if (ids[di] > 0) {
            const float4* p = reinterpret_cast<const float4*>(
                g_eo1 + (size_t)(ids[di] - 1) * 256 + lane * 8);
            float4 x = p[0], y = p[1];
            float wg = wv[di] * inv;
            o[0] += wg * x.x; o[1] += wg * x.y; o[2] += wg * x.z; o[3] += wg * x.w;
            o[4] += wg * y.x; o[5] += wg * y.y; o[6] += wg * y.z; o[7] += wg * y.w;
        }
    }
    float* dst = g_no1 + (size_t)n * 256 + lane * 8;
    *reinterpret_cast<float4*>(dst) =
        make_float4(eluf(o[0]), eluf(o[1]), eluf(o[2]), eluf(o[3]));
    *reinterpret_cast<float4*>(dst + 4) =
        make_float4(eluf(o[4]), eluf(o[5]), eluf(o[6]), eluf(o[7]));
}

// ---------------- layer2 edge attention ----------------
__global__ __launch_bounds__(256)
void edge_attn2(const int* __restrict__ el, const float* __restrict__ a2o) {
    int e = blockIdx.x * 8 + (threadIdx.x >> 5);
    if (e >= N_EDGES_C) return;
    int lane = threadIdx.x & 31;
    float se = g_se2[e];
    int ids[MAX_ARITY];
    float s[MAX_ARITY];
#pragma unroll
    for (int ai = 0; ai < MAX_ARITY; ai++) ids[ai] = el[e * MAX_ARITY + ai];
#pragma unroll
    for (int ai = 0; ai < MAX_ARITY; ai++)
        s[ai] = (ids[ai] > 0) ? lreluf(se + g_pn2[ids[ai] - 1]) : -1e9f;
    float m = s[0];
#pragma unroll
    for (int ai = 1; ai < MAX_ARITY; ai++) m = fmaxf(m, s[ai]);
    float wv[MAX_ARITY], den = 0.f;
#pragma unroll
    for (int ai = 0; ai < MAX_ARITY; ai++) { wv[ai] = expf(s[ai] - m); den += wv[ai]; }
    float inv = 1.f / den;
    float o[4] = {};
#pragma unroll
    for (int ai = 0; ai < MAX_ARITY; ai++) {
        if (ids[ai] > 0) {
            float4 x = *reinterpret_cast<const float4*>(
                g_hn2 + (size_t)(ids[ai] - 1) * 128 + lane * 4);
            float wg = wv[ai] * inv;
            o[0] += wg * x.x; o[1] += wg * x.y; o[2] += wg * x.z; o[3] += wg * x.w;
        }
    }
    *reinterpret_cast<float4*>(g_eo2 + (size_t)e * 128 + lane * 4) =
        make_float4(o[0], o[1], o[2], o[3]);
    float pe = 0.f;
#pragma unroll
    for (int i = 0; i < 4; i++) pe += o[i] * a2o[128 + lane * 4 + i];
    pe = warp_sum(pe);
    if (lane == 0) g_pe2[e] = pe;
}

// ---------------- layer2 node attention ----------------
__global__ __launch_bounds__(256)
void node_attn2(const int* __restrict__ nl) {
    int n = blockIdx.x * 8 + (threadIdx.x >> 5);
    if (n >= N_NODES_C) return;
    int lane = threadIdx.x & 31;
    float sn = g_sn2[n];
    int ids[MAX_DEG];
    float s[MAX_DEG];
#pragma unroll
    for (int di = 0; di < MAX_DEG; di++) ids[di] = nl[n * MAX_DEG + di];
#pragma unroll
    for (int di = 0; di < MAX_DEG; di++)
        s[di] = (ids[di] > 0) ? lreluf(sn + g_pe2[ids[di] - 1]) : -1e9f;
    float m = s[0];
#pragma unroll
    for (int di = 1; di < MAX_DEG; di++) m = fmaxf(m, s[di]);
    float wv[MAX_DEG], den = 0.f;
#pragma unroll
    for (int di = 0; di < MAX_DEG; di++) { wv[di] = expf(s[di] - m); den += wv[di]; }
    float inv = 1.f / den;
    float o[4] = {};
#pragma unroll
    for (int di = 0; di < MAX_DEG; di++) {
        if (ids[di] > 0) {
            float4 x = *reinterpret_cast<const float4*>(
                g_eo2 + (size_t)(ids[di] - 1) * 128 + lane * 4);
            float wg = wv[di] * inv;
            o[0] += wg * x.x; o[1] += wg * x.y; o[2] += wg * x.z; o[3] += wg * x.w;
        }
    }
    *reinterpret_cast<float4*>(g_no2 + (size_t)n * 128 + lane * 4) =
        make_float4(o[0], o[1], o[2], o[3]);
}

// ---------------- final batch gather ----------------
__global__ __launch_bounds__(128)
void gather_out(const int* __restrict__ bi, float* __restrict__ out) {
    int b = blockIdx.x;
    int t = threadIdx.x;
    __shared__ int ids[7];
    __shared__ int lastnz;
    if (t < 7) ids[t] = bi[b * 7 + t];
    __syncthreads();
    if (t == 0) {
        int ln = 0;
#pragma unroll
        for (int j = 1; j < 7; j++) if (ids[j] != 0) ln = j;
        lastnz = ln;
    }
    __syncthreads();
    int ln = lastnz;
    out[(size_t)b * 896 + t] = eluf(g_eo2[(size_t)(ids[0] - 1) * 128 + t]);
#pragma unroll
    for (int a = 1; a < 7; a++) {
        int nid = ids[a] - 1;
        if (nid < 0) nid += N_NODES_C;
        float g = eluf(g_no2[(size_t)nid * 128 + t]);
        out[(size_t)b * 896 + a * 128 + t] = (a <= ln) ? g : 1.0f;
    }
}

// ---------------- launch ----------------
extern "C" void kernel_launch(void* const* d_in, const int* in_sizes, int n_in,
                              void* d_out, int out_size) {
    (void)in_sizes; (void)n_in; (void)out_size;
    const int*   bi    = (const int*)d_in[0];
    const int*   el    = (const int*)d_in[1];
    const int*   nl    = (const int*)d_in[2];
    const float* nemb  = (const float*)d_in[3];
    const float* eemb  = (const float*)d_in[4];
    const float* Wn    = (const float*)d_in[5];
    const float* We    = (const float*)d_in[6];
    const float* a1    = (const float*)d_in[7];
    const float* a2    = (const float*)d_in[8];
    const float* Wn_o  = (const float*)d_in[9];
    const float* We_o  = (const float*)d_in[10];
    const float* a1_o  = (const float*)d_in[11];
    const float* a2_o  = (const float*)d_in[12];
    float* out = (float*)d_out;

    float *hn1, *he1, *eo1, *no1, *hn2, *he2;
    float *pn1, *sn1, *se1, *pn2, *sn2, *se2;
    float *wpn1, *wqn1, *wpe1, *wpn2, *wqn2, *wpe2;
    __nv_bfloat16 *bt1n, *bt1e, *bt2n, *bt2e;
    cudaGetSymbolAddress((void**)&hn1, g_hn1);
    cudaGetSymbolAddress((void**)&he1, g_he1);
    cudaGetSymbolAddress((void**)&eo1, g_eo1);
    cudaGetSymbolAddress((void**)&no1, g_no1);
    cudaGetSymbolAddress((void**)&hn2, g_hn2);
    cudaGetSymbolAddress((void**)&he2, g_he2);
    cudaGetSymbolAddress((void**)&pn1, g_pn1);
    cudaGetSymbolAddress((void**)&sn1, g_sn1);
    cudaGetSymbolAddress((void**)&se1, g_se1);
    cudaGetSymbolAddress((void**)&pn2, g_pn2);
    cudaGetSymbolAddress((void**)&sn2, g_sn2);
    cudaGetSymbolAddress((void**)&se2, g_se2);
    cudaGetSymbolAddress((void**)&wpn1, g_wpn1);
    cudaGetSymbolAddress((void**)&wqn1, g_wqn1);
    cudaGetSymbolAddress((void**)&wpe1, g_wpe1);
    cudaGetSymbolAddress((void**)&wpn2, g_wpn2);
    cudaGetSymbolAddress((void**)&wqn2, g_wqn2);
    cudaGetSymbolAddress((void**)&wpe2, g_wpe2);
    cudaGetSymbolAddress((void**)&bt1n, g_Bt1n);
    cudaGetSymbolAddress((void**)&bt1e, g_Bt1e);
    cudaGetSymbolAddress((void**)&bt2n, g_Bt2n);
    cudaGetSymbolAddress((void**)&bt2e, g_Bt2e);

    prep<<<782, 256>>>(Wn, We, Wn_o, We_o, a1, a2, a1_o, a2_o);

    // layer1 projections + fused scores
    gemm_tc<false, 2><<<dim3(391, 4), 256>>>(nemb, bt1n, hn1, N_NODES_C, 256, 128,
                                             wpn1, wqn1, pn1, sn1, 4);
    gemm_tc<false, 1><<<dim3(196, 4), 256>>>(eemb, bt1e, he1, N_EDGES_C, 256, 128,
                                             wpe1, nullptr, se1, nullptr, 4);

    edge_attn1<<<3125, 256>>>(el, a2);
    node_attn1<<<6250, 256>>>(nl);

    // layer2 projections + fused scores (edge input ELU'd on the fly)
    gemm_tc<false, 2><<<dim3(391, 2), 256>>>(no1, bt2n, hn2, N_NODES_C, 128, 256,
                                             wpn2, wqn2, pn2, sn2, 1);
    gemm_tc<true, 1><<<dim3(196, 2), 256>>>(eo1, bt2e, he2, N_EDGES_C, 128, 256,
                                            wpe2, nullptr, se2, nullptr, 1);

    edge_attn2<<<3125, 256>>>(el, a1_o);
    node_attn2<<<6250, 256>>>(nl);

    gather_out<<<BATCH_C, 128>>>(bi, out);
}